// round 1
// baseline (speedup 1.0000x reference)
#include <cuda_runtime.h>

#define KAPn 8
#define Nn   2000
#define NPn  2048
#define N0n  1000
#define Mn   10000
#define Dn   8
#define NBn  128
#define NSTEPS 16        // NPn / NBn
#define NUGf 1e-6f

// ---------------- device scratch (static, no runtime allocation) ----------------
__device__ float g_K[KAPn * NPn * NPn];     // padded covariance / Cholesky factors (134 MB)
__device__ float g_Knt[KAPn * N0n * Nn];    // cross covariance (64 MB)
__device__ float g_rhs[KAPn * NPn];         // rhs -> alpha (in place)
__device__ float g_ghat[KAPn * N0n];
__device__ float g_ils[KAPn * Dn];          // inverse lengthscales
__device__ float g_amp[KAPn];               // exp(lmb[D])

__device__ __forceinline__ float warp_reduce(float v) {
#pragma unroll
    for (int s = 16; s > 0; s >>= 1) v += __shfl_xor_sync(0xffffffffu, v, s);
    return v;
}

// ---------------- small prep: lengthscales + amplitude ----------------
__global__ void prep_kernel(const float* __restrict__ Lmb) {
    int t = threadIdx.x;
    if (t < KAPn * Dn) {
        int k = t / Dn, d = t % Dn;
        g_ils[t] = 1.0f / expf(Lmb[k * (Dn + 1) + d]);
    }
    if (t < KAPn) g_amp[t] = expf(Lmb[t * (Dn + 1) + Dn]);
}

// ---------------- build K_tt (padded to 2048 with identity) ----------------
__global__ void build_ktt_kernel(const float* __restrict__ theta) {
    int kap = blockIdx.z;
    int i = blockIdx.y * 16 + threadIdx.y;
    int j = blockIdx.x * 16 + threadIdx.x;
    __shared__ float ti[16][Dn], tj[16][Dn];
    int t = threadIdx.y * 16 + threadIdx.x;
    if (t < 16 * Dn) {
        int r = t / Dn, d = t % Dn;
        int gi = blockIdx.y * 16 + r;
        ti[r][d] = (gi < Nn) ? theta[gi * Dn + d] : 0.f;
        int gj = blockIdx.x * 16 + r;
        tj[r][d] = (gj < Nn) ? theta[gj * Dn + d] : 0.f;
    }
    __syncthreads();
    float v;
    if (i < Nn && j < Nn) {
        const float* ils = g_ils + kap * Dn;
        float prod = 1.f, ssum = 0.f;
#pragma unroll
        for (int d = 0; d < Dn; d++) {
            float S = fabsf(ti[threadIdx.y][d] - tj[threadIdx.x][d]) * ils[d];
            prod *= (1.f + S);
            ssum += S;
        }
        v = g_amp[kap] * prod * expf(-ssum);
        if (i == j) v += NUGf * g_amp[kap];
    } else {
        v = (i == j) ? 1.f : 0.f;
    }
    g_K[kap * NPn * NPn + i * NPn + j] = v;
}

// ---------------- build K_nt ----------------
__global__ void build_knt_kernel(const float* __restrict__ theta0,
                                 const float* __restrict__ theta) {
    int kap = blockIdx.z;
    int o = blockIdx.y * 16 + threadIdx.y;
    int n = blockIdx.x * 16 + threadIdx.x;
    __shared__ float to_[16][Dn], tn_[16][Dn];
    int t = threadIdx.y * 16 + threadIdx.x;
    if (t < 16 * Dn) {
        int r = t / Dn, d = t % Dn;
        int go = blockIdx.y * 16 + r;
        to_[r][d] = (go < N0n) ? theta0[go * Dn + d] : 0.f;
        int gn = blockIdx.x * 16 + r;
        tn_[r][d] = (gn < Nn) ? theta[gn * Dn + d] : 0.f;
    }
    __syncthreads();
    if (o >= N0n || n >= Nn) return;
    const float* ils = g_ils + kap * Dn;
    float prod = 1.f, ssum = 0.f;
#pragma unroll
    for (int d = 0; d < Dn; d++) {
        float S = fabsf(to_[threadIdx.y][d] - tn_[threadIdx.x][d]) * ils[d];
        prod *= (1.f + S);
        ssum += S;
    }
    g_Knt[(kap * N0n + o) * Nn + n] = g_amp[kap] * prod * expf(-ssum);
}

// ---------------- rhs init ----------------
__global__ void init_rhs_kernel(const float* __restrict__ Mu) {
    int idx = blockIdx.x * blockDim.x + threadIdx.x;
    if (idx >= KAPn * NPn) return;
    int kap = idx / NPn, i = idx % NPn;
    g_rhs[idx] = (i < Nn) ? Mu[kap * Nn + i] : 0.f;
}

// ---------------- Cholesky: factor 128x128 diagonal block ----------------
// One block per kap; 128 threads, thread t owns row t. Clamped pivots guard the
// ~1e9 condition number against fp32 breakdown (NaN).
__global__ void potf2_kernel(int off) {
    extern __shared__ float sh[];   // [128][129]
    int kap = blockIdx.x;
    int t = threadIdx.x;
    float* A = g_K + kap * NPn * NPn + off * NPn + off;
    float dmin = 1e-4f * g_amp[kap];
    for (int r = 0; r < NBn; r++) sh[r * (NBn + 1) + t] = A[r * NPn + t];
    __syncthreads();
    for (int j = 0; j < NBn; j++) {
        if (t == j) {
            float d = sh[j * (NBn + 1) + j];
            if (!(d > dmin)) d = dmin;      // pivot clamp (also catches NaN)
            sh[j * (NBn + 1) + j] = sqrtf(d);
        }
        __syncthreads();
        float dj = sh[j * (NBn + 1) + j];
        if (t > j) sh[t * (NBn + 1) + j] /= dj;
        __syncthreads();
        if (t > j) {
            float ltj = sh[t * (NBn + 1) + j];
            for (int i2 = j + 1; i2 <= t; i2++)
                sh[t * (NBn + 1) + i2] -= ltj * sh[i2 * (NBn + 1) + j];
        }
    }
    __syncthreads();
    for (int r = 0; r < NBn; r++) A[r * NPn + t] = sh[r * (NBn + 1) + t];
}

// ---------------- Cholesky: panel trsm  L21 = A21 * L11^{-T} ----------------
// Warp per row; x distributed across lanes (lane owns i = lane + 32q).
__global__ void trsm_kernel(int off, int mrows) {
    int kap = blockIdx.y;
    int gw = (blockIdx.x * blockDim.x + threadIdx.x) >> 5;
    int lane = threadIdx.x & 31;
    if (gw >= mrows) return;
    int row = off + NBn + gw;
    float* G = g_K + kap * NPn * NPn;
    const float* Lbase = G + off * NPn + off;   // L11
    float* arow = G + row * NPn + off;
    float x[4];
#pragma unroll
    for (int q = 0; q < 4; q++) x[q] = arow[lane + 32 * q];
#pragma unroll
    for (int qj = 0; qj < 4; qj++) {
        for (int jl = 0; jl < 32; jl++) {
            int j = 32 * qj + jl;
            const float* Lrow = Lbase + j * NPn;
            float part = 0.f;
#pragma unroll
            for (int q = 0; q < qj; q++) part += x[q] * __ldg(&Lrow[lane + 32 * q]);
            if (lane < jl) part += x[qj] * __ldg(&Lrow[lane + 32 * qj]);
            part = warp_reduce(part);
            float diag = __ldg(&Lrow[j]);
            if (lane == jl) x[qj] = (x[qj] - part) / diag;
        }
    }
#pragma unroll
    for (int q = 0; q < 4; q++) arow[lane + 32 * q] = x[q];
}

// ---------------- Cholesky: trailing SYRK update (lower-tri tiles only) ------
// C(128x128) -= A(128x128) * B(128x128)^T with A,B = panel row-blocks.
__global__ void __launch_bounds__(256) syrk_kernel(int off, int nb) {
    int kap = blockIdx.y;
    int tt = blockIdx.x;
    int bi = 0, rem = tt;
    while (rem > bi) { rem -= (bi + 1); bi++; }
    int bj = rem;                     // bi >= bj
    int r0 = off + NBn;
    int R = r0 + bi * NBn, C = r0 + bj * NBn;
    float* G = g_K + kap * NPn * NPn;

    __shared__ float As[16][NBn + 4];
    __shared__ float Bs[16][NBn + 4];
    float acc[8][8];
#pragma unroll
    for (int m = 0; m < 8; m++)
#pragma unroll
        for (int n = 0; n < 8; n++) acc[m][n] = 0.f;

    int tid = threadIdx.x;
    int tr = tid >> 4, tc = tid & 15;

    for (int kk = 0; kk < NBn; kk += 16) {
#pragma unroll
        for (int s = 0; s < 2; s++) {
            int fi = tid + s * 256;       // float4 index in [0,512)
            int row = fi >> 2;
            int kq = (fi & 3) * 4;
            float4 av = *(const float4*)(G + (R + row) * NPn + off + kk + kq);
            As[kq + 0][row] = av.x; As[kq + 1][row] = av.y;
            As[kq + 2][row] = av.z; As[kq + 3][row] = av.w;
            float4 bv = *(const float4*)(G + (C + row) * NPn + off + kk + kq);
            Bs[kq + 0][row] = bv.x; Bs[kq + 1][row] = bv.y;
            Bs[kq + 2][row] = bv.z; Bs[kq + 3][row] = bv.w;
        }
        __syncthreads();
#pragma unroll
        for (int k = 0; k < 16; k++) {
            float ar[8], br[8];
#pragma unroll
            for (int m = 0; m < 8; m++) ar[m] = As[k][tr * 8 + m];
#pragma unroll
            for (int n = 0; n < 8; n++) br[n] = Bs[k][tc * 8 + n];
#pragma unroll
            for (int m = 0; m < 8; m++)
#pragma unroll
                for (int n = 0; n < 8; n++) acc[m][n] += ar[m] * br[n];
        }
        __syncthreads();
    }
#pragma unroll
    for (int m = 0; m < 8; m++) {
        float* crow = G + (R + tr * 8 + m) * NPn + C + tc * 8;
#pragma unroll
        for (int n = 0; n < 8; n++) crow[n] -= acc[m][n];
    }
}

// ---------------- forward solve: diag block (column sweep) ----------------
__global__ void fwd_diag_kernel(int off) {
    extern __shared__ float sh[];    // [128][129] + xs[128]
    float* xs = sh + NBn * (NBn + 1);
    int kap = blockIdx.x, t = threadIdx.x;
    const float* A = g_K + kap * NPn * NPn + off * NPn + off;
    float* r = g_rhs + kap * NPn + off;
    for (int rr = 0; rr < NBn; rr++) sh[rr * (NBn + 1) + t] = A[rr * NPn + t];
    float rv = r[t];
    __syncthreads();
    for (int j = 0; j < NBn; j++) {
        if (t == j) xs[j] = rv / sh[j * (NBn + 1) + j];
        __syncthreads();
        if (t > j) rv -= sh[t * (NBn + 1) + j] * xs[j];
        __syncthreads();
    }
    r[t] = xs[t];
}

// forward update: rhs[row] -= L[row, off:off+128] . y[off:off+128]  (warp/row)
__global__ void fwd_update_kernel(int off, int mrows) {
    int kap = blockIdx.y;
    int gw = (blockIdx.x * blockDim.x + threadIdx.x) >> 5;
    int lane = threadIdx.x & 31;
    if (gw >= mrows) return;
    int row = off + NBn + gw;
    const float* G = g_K + kap * NPn * NPn;
    const float* y = g_rhs + kap * NPn + off;
    const float* Lr = G + row * NPn + off;
    float part = 0.f;
#pragma unroll
    for (int q = 0; q < 4; q++) part += Lr[lane + 32 * q] * y[lane + 32 * q];
    part = warp_reduce(part);
    if (lane == 0) g_rhs[kap * NPn + row] -= part;
}

// ---------------- backward solve: diag block (L^T, column sweep) -------------
__global__ void bwd_diag_kernel(int off) {
    extern __shared__ float sh[];
    float* xs = sh + NBn * (NBn + 1);
    int kap = blockIdx.x, t = threadIdx.x;
    const float* A = g_K + kap * NPn * NPn + off * NPn + off;
    float* r = g_rhs + kap * NPn + off;
    for (int rr = 0; rr < NBn; rr++) sh[rr * (NBn + 1) + t] = A[rr * NPn + t];
    float rv = r[t];
    __syncthreads();
    for (int j = NBn - 1; j >= 0; j--) {
        if (t == j) xs[j] = rv / sh[j * (NBn + 1) + j];
        __syncthreads();
        if (t < j) rv -= sh[j * (NBn + 1) + t] * xs[j];   // L^T[t][j] = L[j][t]
        __syncthreads();
    }
    r[t] = xs[t];
}

// backward update: rhs[j] -= sum_i L[off+i][j] * x[off+i],  j < off (coalesced)
__global__ void bwd_update_kernel(int off) {
    int idx = blockIdx.x * blockDim.x + threadIdx.x;
    int kap = blockIdx.y;
    if (idx >= off) return;
    const float* G = g_K + kap * NPn * NPn;
    const float* x = g_rhs + kap * NPn + off;
    float s = 0.f;
#pragma unroll 8
    for (int i = 0; i < NBn; i++) s += G[(off + i) * NPn + idx] * __ldg(&x[i]);
    g_rhs[kap * NPn + idx] -= s;
}

// ---------------- ghat = K_nt @ alpha (warp per output) ----------------
__global__ void ghat_kernel() {
    int gw = (blockIdx.x * blockDim.x + threadIdx.x) >> 5;
    int lane = threadIdx.x & 31;
    if (gw >= KAPn * N0n) return;
    int kap = gw / N0n, o = gw % N0n;
    const float* Kr = g_Knt + (kap * N0n + o) * Nn;
    const float* a = g_rhs + kap * NPn;
    float s = 0.f;
    for (int i = lane; i < Nn; i += 32) s += Kr[i] * a[i];
    s = warp_reduce(s);
    if (lane == 0) g_ghat[kap * N0n + o] = s;
}

// ---------------- fhat = psi + Phi @ ghat ----------------
__global__ void fhat_kernel(const float* __restrict__ psi,
                            const float* __restrict__ Phi,
                            float* __restrict__ out) {
    int idx = blockIdx.x * blockDim.x + threadIdx.x;
    if (idx >= Mn * N0n) return;
    int m = idx / N0n, o = idx % N0n;
    float s = psi[m];
#pragma unroll
    for (int k = 0; k < KAPn; k++) s += Phi[m * KAPn + k] * g_ghat[k * N0n + o];
    out[idx] = s;
}

// ---------------- host launch ----------------
extern "C" void kernel_launch(void* const* d_in, const int* in_sizes, int n_in,
                              void* d_out, int out_size) {
    const float* theta0 = (const float*)d_in[0];
    const float* Lmb    = (const float*)d_in[1];
    // d_in[2] = lsigma2 (unused by fhat)
    const float* Mu     = (const float*)d_in[3];
    const float* psi    = (const float*)d_in[4];
    const float* Phi    = (const float*)d_in[5];
    const float* theta  = (const float*)d_in[6];
    float* out = (float*)d_out;

    const int SMEM_POTF2 = NBn * (NBn + 1) * (int)sizeof(float);            // 66048
    const int SMEM_DIAG  = (NBn * (NBn + 1) + NBn) * (int)sizeof(float);    // 66560
    cudaFuncSetAttribute(potf2_kernel,    cudaFuncAttributeMaxDynamicSharedMemorySize, SMEM_POTF2);
    cudaFuncSetAttribute(fwd_diag_kernel, cudaFuncAttributeMaxDynamicSharedMemorySize, SMEM_DIAG);
    cudaFuncSetAttribute(bwd_diag_kernel, cudaFuncAttributeMaxDynamicSharedMemorySize, SMEM_DIAG);

    prep_kernel<<<1, 128>>>(Lmb);
    build_ktt_kernel<<<dim3(NPn / 16, NPn / 16, KAPn), dim3(16, 16)>>>(theta);
    build_knt_kernel<<<dim3((Nn + 15) / 16, (N0n + 15) / 16, KAPn), dim3(16, 16)>>>(theta0, theta);
    init_rhs_kernel<<<(KAPn * NPn + 255) / 256, 256>>>(Mu);

    // Blocked Cholesky
    for (int k = 0; k < NSTEPS; k++) {
        int off = k * NBn;
        potf2_kernel<<<KAPn, NBn, SMEM_POTF2>>>(off);
        int m = NPn - off - NBn;
        if (m > 0) {
            dim3 g((m + 7) / 8, KAPn);
            trsm_kernel<<<g, 256>>>(off, m);
            int nb = m / NBn;
            syrk_kernel<<<dim3(nb * (nb + 1) / 2, KAPn), 256>>>(off, nb);
        }
    }
    // Forward solve L y = Mu
    for (int k = 0; k < NSTEPS; k++) {
        int off = k * NBn;
        fwd_diag_kernel<<<KAPn, NBn, SMEM_DIAG>>>(off);
        int m = NPn - off - NBn;
        if (m > 0) {
            dim3 g((m + 7) / 8, KAPn);
            fwd_update_kernel<<<g, 256>>>(off, m);
        }
    }
    // Backward solve L^T alpha = y
    for (int k = NSTEPS - 1; k >= 0; k--) {
        int off = k * NBn;
        bwd_diag_kernel<<<KAPn, NBn, SMEM_DIAG>>>(off);
        if (off > 0) {
            dim3 g((off + 255) / 256, KAPn);
            bwd_update_kernel<<<g, 256>>>(off);
        }
    }

    ghat_kernel<<<(KAPn * N0n * 32 + 255) / 256, 256>>>();
    fhat_kernel<<<(Mn * N0n + 255) / 256, 256>>>(psi, Phi, out);
}

// round 3
// speedup vs baseline: 1.3041x; 1.3041x over previous
#include <cuda_runtime.h>

#define KAPn 8
#define Nn   2000
#define NPn  2048
#define N0n  1000
#define Mn   10000
#define Dn   8
#define NBn  128
#define NSTEPS 16        // NPn / NBn
#define NUGf 1e-6f

// ---------------- device scratch (static, no runtime allocation) ----------------
__device__ float g_K[KAPn * NPn * NPn];     // padded covariance / Cholesky factors
__device__ float g_Knt[KAPn * N0n * Nn];    // cross covariance
__device__ float g_rhs[KAPn * NPn];         // rhs -> alpha (in place)
__device__ float g_invd[KAPn * NPn];        // 1 / L[j][j]
__device__ float g_ghat[KAPn * N0n];
__device__ float g_ils[KAPn * Dn];          // inverse lengthscales
__device__ float g_amp[KAPn];               // exp(lmb[D])

__device__ __forceinline__ float warp_reduce(float v) {
#pragma unroll
    for (int s = 16; s > 0; s >>= 1) v += __shfl_xor_sync(0xffffffffu, v, s);
    return v;
}

// exp(-s) for s >= 0, FMA-pipe only (no MUFU). |rel err| ~3e-7.
__device__ __forceinline__ float fast_expn(float s) {
    float z = s * -1.4426950408889634f;          // log2(e)
    z = fmaxf(z, -125.0f);                       // underflow guard
    int e = __float2int_rn(z);
    float f = z - (float)e;                      // f in [-0.5, 0.5]
    // 2^f = exp(f ln2): Taylor deg 6
    float p = fmaf(f, 1.5403530e-4f, 1.3333558e-3f);
    p = fmaf(f, p, 9.6181291e-3f);
    p = fmaf(f, p, 5.5504109e-2f);
    p = fmaf(f, p, 2.4022651e-1f);
    p = fmaf(f, p, 6.9314718e-1f);
    p = fmaf(f, p, 1.0f);
    return p * __int_as_float((e + 127) << 23);
}

// ---------------- small prep: lengthscales + amplitude ----------------
__global__ void prep_kernel(const float* __restrict__ Lmb) {
    int t = threadIdx.x;
    if (t < KAPn * Dn) {
        int k = t / Dn, d = t % Dn;
        g_ils[t] = 1.0f / expf(Lmb[k * (Dn + 1) + d]);
    }
    if (t < KAPn) g_amp[t] = expf(Lmb[t * (Dn + 1) + Dn]);
}

// ---------------- build K_tt (padded to 2048 with identity) ----------------
__global__ void build_ktt_kernel(const float* __restrict__ theta) {
    int kap = blockIdx.z;
    int i = blockIdx.y * 16 + threadIdx.y;
    int j = blockIdx.x * 16 + threadIdx.x;
    __shared__ float ti[16][Dn], tj[16][Dn];
    int t = threadIdx.y * 16 + threadIdx.x;
    if (t < 16 * Dn) {
        int r = t / Dn, d = t % Dn;
        int gi = blockIdx.y * 16 + r;
        ti[r][d] = (gi < Nn) ? theta[gi * Dn + d] : 0.f;
        int gj = blockIdx.x * 16 + r;
        tj[r][d] = (gj < Nn) ? theta[gj * Dn + d] : 0.f;
    }
    __syncthreads();
    float v;
    if (i < Nn && j < Nn) {
        const float* ils = g_ils + kap * Dn;
        float prod = 1.f, ssum = 0.f;
#pragma unroll
        for (int d = 0; d < Dn; d++) {
            float S = fabsf(ti[threadIdx.y][d] - tj[threadIdx.x][d]) * ils[d];
            prod *= (1.f + S);
            ssum += S;
        }
        v = g_amp[kap] * prod * fast_expn(ssum);
        if (i == j) v += NUGf * g_amp[kap];
    } else {
        v = (i == j) ? 1.f : 0.f;
    }
    g_K[kap * NPn * NPn + i * NPn + j] = v;
}

// ---------------- build K_nt ----------------
__global__ void build_knt_kernel(const float* __restrict__ theta0,
                                 const float* __restrict__ theta) {
    int kap = blockIdx.z;
    int o = blockIdx.y * 16 + threadIdx.y;
    int n = blockIdx.x * 16 + threadIdx.x;
    __shared__ float to_[16][Dn], tn_[16][Dn];
    int t = threadIdx.y * 16 + threadIdx.x;
    if (t < 16 * Dn) {
        int r = t / Dn, d = t % Dn;
        int go = blockIdx.y * 16 + r;
        to_[r][d] = (go < N0n) ? theta0[go * Dn + d] : 0.f;
        int gn = blockIdx.x * 16 + r;
        tn_[r][d] = (gn < Nn) ? theta[gn * Dn + d] : 0.f;
    }
    __syncthreads();
    if (o >= N0n || n >= Nn) return;
    const float* ils = g_ils + kap * Dn;
    float prod = 1.f, ssum = 0.f;
#pragma unroll
    for (int d = 0; d < Dn; d++) {
        float S = fabsf(to_[threadIdx.y][d] - tn_[threadIdx.x][d]) * ils[d];
        prod *= (1.f + S);
        ssum += S;
    }
    g_Knt[(kap * N0n + o) * Nn + n] = g_amp[kap] * prod * fast_expn(ssum);
}

// ---------------- rhs init ----------------
__global__ void init_rhs_kernel(const float* __restrict__ Mu) {
    int idx = blockIdx.x * blockDim.x + threadIdx.x;
    if (idx >= KAPn * NPn) return;
    int kap = idx / NPn, i = idx % NPn;
    g_rhs[idx] = (i < Nn) ? Mu[kap * Nn + i] : 0.f;
}

// ---------------- Cholesky: factor 128x128 diag block (deferred scaling) -----
// 512 threads: thread = (row t, quarter q). 2 barriers per column.
// Columns stay UNSCALED through the loop; Schur update uses 1/d; all scaling
// applied in one final pass. Stores 1/L[j][j] to g_invd.
__global__ void __launch_bounds__(512) potf2_kernel(int off) {
    extern __shared__ float sm[];
    float* sh = sm;                  // [128][129]
    float* sdi = sm + NBn * (NBn + 1);
    int kap = blockIdx.x;
    int tid = threadIdx.x;
    int t = tid & 127, q = tid >> 7;
    float* A = g_K + (size_t)kap * NPn * NPn + (size_t)off * NPn + off;
    for (int idx = tid; idx < NBn * NBn; idx += 512) {
        int r = idx >> 7, c = idx & 127;
        sh[r * (NBn + 1) + c] = A[r * NPn + c];
    }
    float dmin = 1e-4f * g_amp[kap];
    __syncthreads();
    for (int j = 0; j < NBn; j++) {
        if (tid == 0) {
            float d = sh[j * (NBn + 1) + j];
            if (!(d > dmin)) d = dmin;       // pivot clamp (also catches NaN)
            float s = sqrtf(d);
            sh[j * (NBn + 1) + j] = s;
            sdi[j] = 1.0f / s;
        }
        __syncthreads();
        if (t > j) {
            float rs = sdi[j];
            float ltj = sh[t * (NBn + 1) + j] * (rs * rs);
            int lo = q * 32; if (lo < j + 1) lo = j + 1;
            int hi = q * 32 + 31; if (hi > t) hi = t;
            for (int i = lo; i <= hi; i++)
                sh[t * (NBn + 1) + i] -= ltj * sh[i * (NBn + 1) + j];
        }
        __syncthreads();
    }
    // final scaling of strictly-lower part + writeback
    for (int idx = tid; idx < NBn * NBn; idx += 512) {
        int r = idx >> 7, c = idx & 127;
        float v = sh[r * (NBn + 1) + c];
        if (r > c) v *= sdi[c];
        A[r * NPn + c] = v;
    }
    if (tid < NBn) g_invd[kap * NPn + off + tid] = sdi[tid];
}

// ---------------- Cholesky panel trsm: L21 = A21 * L11^{-T} ----------------
// CTA = 32 rows (8 warps x 4 rows each); L11 staged in padded shared.
// Right-looking substitution: 1 shfl + <=4 FMA + conflict-free column LDS / col.
__global__ void __launch_bounds__(256) trsm_kernel(int off, int m) {
    extern __shared__ float sm[];
    float* Ls = sm;                  // [128][129]
    float* sinv = sm + NBn * (NBn + 1);
    int kap = blockIdx.y;
    int tid = threadIdx.x;
    float* G = g_K + (size_t)kap * NPn * NPn;
    const float* L11 = G + (size_t)off * NPn + off;
    for (int idx = tid; idx < NBn * NBn; idx += 256) {
        int r = idx >> 7, c = idx & 127;
        Ls[r * (NBn + 1) + c] = L11[r * NPn + c];
    }
    if (tid < NBn) sinv[tid] = g_invd[kap * NPn + off + tid];
    __syncthreads();
    int w = tid >> 5, lane = tid & 31;
    int row0 = off + NBn + blockIdx.x * 32 + w * 4;
    for (int rr = 0; rr < 4; rr++) {
        float* arow = G + (size_t)(row0 + rr) * NPn + off;
        float x[4];
#pragma unroll
        for (int qq = 0; qq < 4; qq++) x[qq] = arow[lane + 32 * qq];
#pragma unroll
        for (int qj = 0; qj < 4; qj++) {
#pragma unroll
            for (int lj = 0; lj < 32; lj++) {
                int j = qj * 32 + lj;
                if (lane == lj) x[qj] *= sinv[j];
                float xj = __shfl_sync(0xffffffffu, x[qj], lj);
                if (lane > lj) x[qj] -= xj * Ls[(lane + 32 * qj) * (NBn + 1) + j];
#pragma unroll
                for (int qq = qj + 1; qq < 4; qq++)
                    x[qq] -= xj * Ls[(lane + 32 * qq) * (NBn + 1) + j];
            }
        }
#pragma unroll
        for (int qq = 0; qq < 4; qq++) arow[lane + 32 * qq] = x[qq];
    }
}

// ---------------- Cholesky: trailing SYRK update (lower-tri tiles only) ------
__global__ void __launch_bounds__(256) syrk_kernel(int off, int nb) {
    int kap = blockIdx.y;
    int tt = blockIdx.x;
    int bi = 0, rem = tt;
    while (rem > bi) { rem -= (bi + 1); bi++; }
    int bj = rem;                     // bi >= bj
    int r0 = off + NBn;
    int R = r0 + bi * NBn, C = r0 + bj * NBn;
    float* G = g_K + kap * NPn * NPn;

    __shared__ float As[16][NBn + 4];
    __shared__ float Bs[16][NBn + 4];
    float acc[8][8];
#pragma unroll
    for (int m = 0; m < 8; m++)
#pragma unroll
        for (int n = 0; n < 8; n++) acc[m][n] = 0.f;

    int tid = threadIdx.x;
    int tr = tid >> 4, tc = tid & 15;

    for (int kk = 0; kk < NBn; kk += 16) {
#pragma unroll
        for (int s = 0; s < 2; s++) {
            int fi = tid + s * 256;       // float4 index in [0,512)
            int row = fi >> 2;
            int kq = (fi & 3) * 4;
            float4 av = *(const float4*)(G + (R + row) * NPn + off + kk + kq);
            As[kq + 0][row] = av.x; As[kq + 1][row] = av.y;
            As[kq + 2][row] = av.z; As[kq + 3][row] = av.w;
            float4 bv = *(const float4*)(G + (C + row) * NPn + off + kk + kq);
            Bs[kq + 0][row] = bv.x; Bs[kq + 1][row] = bv.y;
            Bs[kq + 2][row] = bv.z; Bs[kq + 3][row] = bv.w;
        }
        __syncthreads();
#pragma unroll
        for (int k = 0; k < 16; k++) {
            float ar[8], br[8];
#pragma unroll
            for (int m = 0; m < 8; m++) ar[m] = As[k][tr * 8 + m];
#pragma unroll
            for (int n = 0; n < 8; n++) br[n] = Bs[k][tc * 8 + n];
#pragma unroll
            for (int m = 0; m < 8; m++)
#pragma unroll
                for (int n = 0; n < 8; n++) acc[m][n] += ar[m] * br[n];
        }
        __syncthreads();
    }
#pragma unroll
    for (int m = 0; m < 8; m++) {
        float* crow = G + (R + tr * 8 + m) * NPn + C + tc * 8;
#pragma unroll
        for (int n = 0; n < 8; n++) crow[n] -= acc[m][n];
    }
}

// ---------------- fused forward solve: L y = rhs (one CTA per kap) ----------
__global__ void __launch_bounds__(512) fwd_solve_kernel() {
    extern __shared__ float sm[];
    float* Ls = sm;                               // [128][129]
    float* sinv = sm + NBn * (NBn + 1);           // [128]
    float* sr = sinv + NBn;                       // [2048]
    int kap = blockIdx.x;
    int tid = threadIdx.x;
    const float* G = g_K + (size_t)kap * NPn * NPn;
    float* r = g_rhs + kap * NPn;
    for (int i = tid; i < NPn; i += 512) sr[i] = r[i];
    for (int k = 0; k < NSTEPS; k++) {
        int off = k * NBn;
        const float* L11 = G + (size_t)off * NPn + off;
        for (int idx = tid; idx < NBn * NBn; idx += 512) {
            int rr = idx >> 7, c = idx & 127;
            Ls[rr * (NBn + 1) + c] = L11[rr * NPn + c];
        }
        if (tid < NBn) sinv[tid] = g_invd[kap * NPn + off + tid];
        __syncthreads();
        if (tid < 32) {                            // warp 0 does 128-substitution
            int lane = tid;
            float x[4];
#pragma unroll
            for (int qq = 0; qq < 4; qq++) x[qq] = sr[off + lane + 32 * qq];
#pragma unroll
            for (int qj = 0; qj < 4; qj++) {
#pragma unroll
                for (int lj = 0; lj < 32; lj++) {
                    int j = qj * 32 + lj;
                    if (lane == lj) x[qj] *= sinv[j];
                    float xj = __shfl_sync(0xffffffffu, x[qj], lj);
                    if (lane > lj) x[qj] -= xj * Ls[(lane + 32 * qj) * (NBn + 1) + j];
#pragma unroll
                    for (int qq = qj + 1; qq < 4; qq++)
                        x[qq] -= xj * Ls[(lane + 32 * qq) * (NBn + 1) + j];
                }
            }
#pragma unroll
            for (int qq = 0; qq < 4; qq++) sr[off + lane + 32 * qq] = x[qq];
        }
        __syncthreads();
        // update rows below: warp per row
        int wid = tid >> 5, lane = tid & 31;
        for (int row = off + NBn + wid; row < NPn; row += 16) {
            const float* Lr = G + (size_t)row * NPn + off;
            float part = Lr[lane] * sr[off + lane]
                       + Lr[lane + 32] * sr[off + lane + 32]
                       + Lr[lane + 64] * sr[off + lane + 64]
                       + Lr[lane + 96] * sr[off + lane + 96];
            part = warp_reduce(part);
            if (lane == 0) sr[row] -= part;
        }
        __syncthreads();
    }
    for (int i = tid; i < NPn; i += 512) r[i] = sr[i];
}

// ---------------- fused backward solve: L^T x = y (one CTA per kap) ---------
__global__ void __launch_bounds__(512) bwd_solve_kernel() {
    extern __shared__ float sm[];
    float* Ls = sm;
    float* sinv = sm + NBn * (NBn + 1);
    float* sr = sinv + NBn;
    int kap = blockIdx.x;
    int tid = threadIdx.x;
    const float* G = g_K + (size_t)kap * NPn * NPn;
    float* r = g_rhs + kap * NPn;
    for (int i = tid; i < NPn; i += 512) sr[i] = r[i];
    for (int k = NSTEPS - 1; k >= 0; k--) {
        int off = k * NBn;
        const float* L11 = G + (size_t)off * NPn + off;
        for (int idx = tid; idx < NBn * NBn; idx += 512) {
            int rr = idx >> 7, c = idx & 127;
            Ls[rr * (NBn + 1) + c] = L11[rr * NPn + c];
        }
        if (tid < NBn) sinv[tid] = g_invd[kap * NPn + off + tid];
        __syncthreads();
        if (tid < 32) {                            // warp 0: solve L11^T x = r
            int lane = tid;
            float x[4];
#pragma unroll
            for (int qq = 0; qq < 4; qq++) x[qq] = sr[off + lane + 32 * qq];
#pragma unroll
            for (int qj = 3; qj >= 0; qj--) {
#pragma unroll
                for (int lj = 31; lj >= 0; lj--) {
                    int j = qj * 32 + lj;
                    if (lane == lj) x[qj] *= sinv[j];
                    float xj = __shfl_sync(0xffffffffu, x[qj], lj);
                    // update r_i -= L[j][i]*x_j for i<j (row-j read)
                    if (lane < lj) x[qj] -= xj * Ls[j * (NBn + 1) + lane + 32 * qj];
#pragma unroll
                    for (int qq = 0; qq < qj; qq++)
                        x[qq] -= xj * Ls[j * (NBn + 1) + lane + 32 * qq];
                }
            }
#pragma unroll
            for (int qq = 0; qq < 4; qq++) sr[off + lane + 32 * qq] = x[qq];
        }
        __syncthreads();
        // update rhs[0..off): sr[c] -= sum_i L[off+i][c] * x[off+i]  (coalesced)
        for (int c = tid; c < off; c += 512) {
            const float* col = G + (size_t)off * NPn + c;
            float s = 0.f;
#pragma unroll 8
            for (int i = 0; i < NBn; i++) s += col[(size_t)i * NPn] * sr[off + i];
            sr[c] -= s;
        }
        __syncthreads();
    }
    for (int i = tid; i < NPn; i += 512) r[i] = sr[i];
}

// ---------------- ghat = K_nt @ alpha (warp per output) ----------------
__global__ void ghat_kernel() {
    int gw = (blockIdx.x * blockDim.x + threadIdx.x) >> 5;
    int lane = threadIdx.x & 31;
    if (gw >= KAPn * N0n) return;
    int kap = gw / N0n, o = gw % N0n;
    const float* Kr = g_Knt + (kap * N0n + o) * Nn;
    const float* a = g_rhs + kap * NPn;
    float s = 0.f;
    for (int i = lane; i < Nn; i += 32) s += Kr[i] * a[i];
    s = warp_reduce(s);
    if (lane == 0) g_ghat[kap * N0n + o] = s;
}

// ---------------- fhat = psi + Phi @ ghat ----------------
__global__ void fhat_kernel(const float* __restrict__ psi,
                            const float* __restrict__ Phi,
                            float* __restrict__ out) {
    int idx = blockIdx.x * blockDim.x + threadIdx.x;
    if (idx >= Mn * N0n) return;
    int m = idx / N0n, o = idx % N0n;
    float s = psi[m];
#pragma unroll
    for (int k = 0; k < KAPn; k++) s += Phi[m * KAPn + k] * g_ghat[k * N0n + o];
    out[idx] = s;
}

// ---------------- host launch ----------------
extern "C" void kernel_launch(void* const* d_in, const int* in_sizes, int n_in,
                              void* d_out, int out_size) {
    const float* theta0 = (const float*)d_in[0];
    const float* Lmb    = (const float*)d_in[1];
    // d_in[2] = lsigma2 (unused by fhat)
    const float* Mu     = (const float*)d_in[3];
    const float* psi    = (const float*)d_in[4];
    const float* Phi    = (const float*)d_in[5];
    const float* theta  = (const float*)d_in[6];
    float* out = (float*)d_out;

    const int SMEM_FACT  = (NBn * (NBn + 1) + NBn) * (int)sizeof(float);          // 66560
    const int SMEM_SOLVE = (NBn * (NBn + 1) + NBn + NPn) * (int)sizeof(float);    // 74752
    cudaFuncSetAttribute(potf2_kernel,     cudaFuncAttributeMaxDynamicSharedMemorySize, SMEM_FACT);
    cudaFuncSetAttribute(trsm_kernel,      cudaFuncAttributeMaxDynamicSharedMemorySize, SMEM_FACT);
    cudaFuncSetAttribute(fwd_solve_kernel, cudaFuncAttributeMaxDynamicSharedMemorySize, SMEM_SOLVE);
    cudaFuncSetAttribute(bwd_solve_kernel, cudaFuncAttributeMaxDynamicSharedMemorySize, SMEM_SOLVE);

    prep_kernel<<<1, 128>>>(Lmb);
    build_ktt_kernel<<<dim3(NPn / 16, NPn / 16, KAPn), dim3(16, 16)>>>(theta);
    build_knt_kernel<<<dim3((Nn + 15) / 16, (N0n + 15) / 16, KAPn), dim3(16, 16)>>>(theta0, theta);
    init_rhs_kernel<<<(KAPn * NPn + 255) / 256, 256>>>(Mu);

    // Blocked Cholesky
    for (int k = 0; k < NSTEPS; k++) {
        int off = k * NBn;
        potf2_kernel<<<KAPn, 512, SMEM_FACT>>>(off);
        int m = NPn - off - NBn;
        if (m > 0) {
            trsm_kernel<<<dim3(m / 32, KAPn), 256, SMEM_FACT>>>(off, m);
            int nb = m / NBn;
            syrk_kernel<<<dim3(nb * (nb + 1) / 2, KAPn), 256>>>(off, nb);
        }
    }

    fwd_solve_kernel<<<KAPn, 512, SMEM_SOLVE>>>();
    bwd_solve_kernel<<<KAPn, 512, SMEM_SOLVE>>>();

    ghat_kernel<<<(KAPn * N0n * 32 + 255) / 256, 256>>>();
    fhat_kernel<<<(Mn * N0n + 255) / 256, 256>>>(psi, Phi, out);
}

// round 4
// speedup vs baseline: 1.4150x; 1.0851x over previous
#include <cuda_runtime.h>

#define KAPn 8
#define Nn   2000
#define NPn  2048
#define N0n  1000
#define Mn   10000
#define Dn   8
#define NBn  128
#define NSTEPS 16        // NPn / NBn
#define NUGf 1e-6f
#define KCH  32          // syrk k-chunk

// ---------------- device scratch (static, no runtime allocation) ----------------
__device__ float g_K[KAPn * NPn * NPn];     // padded covariance / Cholesky factors
__device__ float g_Knt[KAPn * N0n * Nn];    // cross covariance
__device__ float g_rhs[KAPn * NPn];         // rhs -> alpha (in place)
__device__ float g_invd[KAPn * NPn];        // 1 / L[j][j]
__device__ float g_ghat[KAPn * N0n];

__device__ __forceinline__ float warp_reduce(float v) {
#pragma unroll
    for (int s = 16; s > 0; s >>= 1) v += __shfl_xor_sync(0xffffffffu, v, s);
    return v;
}

// exp(-s) for s >= 0, FMA-pipe only (no MUFU). |rel err| ~3e-7.
__device__ __forceinline__ float fast_expn(float s) {
    float z = s * -1.4426950408889634f;          // log2(e)
    z = fmaxf(z, -125.0f);                       // underflow guard
    int e = __float2int_rn(z);
    float f = z - (float)e;                      // f in [-0.5, 0.5]
    float p = fmaf(f, 1.5403530e-4f, 1.3333558e-3f);
    p = fmaf(f, p, 9.6181291e-3f);
    p = fmaf(f, p, 5.5504109e-2f);
    p = fmaf(f, p, 2.4022651e-1f);
    p = fmaf(f, p, 6.9314718e-1f);
    p = fmaf(f, p, 1.0f);
    return p * __int_as_float((e + 127) << 23);
}

// ---------------- build K_tt (padded to 2048 with identity) ----------------
__global__ void build_ktt_kernel(const float* __restrict__ theta,
                                 const float* __restrict__ Lmb) {
    int kap = blockIdx.z;
    int i = blockIdx.y * 16 + threadIdx.y;
    int j = blockIdx.x * 16 + threadIdx.x;
    __shared__ float ti[16][Dn], tj[16][Dn];
    __shared__ float s_ils[Dn];
    __shared__ float s_amp;
    int t = threadIdx.y * 16 + threadIdx.x;
    if (t < 16 * Dn) {
        int r = t / Dn, d = t % Dn;
        int gi = blockIdx.y * 16 + r;
        ti[r][d] = (gi < Nn) ? theta[gi * Dn + d] : 0.f;
        int gj = blockIdx.x * 16 + r;
        tj[r][d] = (gj < Nn) ? theta[gj * Dn + d] : 0.f;
    }
    if (threadIdx.y == 15) {
        if (threadIdx.x < Dn) s_ils[threadIdx.x] = expf(-Lmb[kap * (Dn + 1) + threadIdx.x]);
        if (threadIdx.x == Dn) s_amp = expf(Lmb[kap * (Dn + 1) + Dn]);
    }
    __syncthreads();
    float v;
    if (i < Nn && j < Nn) {
        float prod = 1.f, ssum = 0.f;
#pragma unroll
        for (int d = 0; d < Dn; d++) {
            float S = fabsf(ti[threadIdx.y][d] - tj[threadIdx.x][d]) * s_ils[d];
            prod *= (1.f + S);
            ssum += S;
        }
        v = s_amp * prod * fast_expn(ssum);
        if (i == j) v += NUGf * s_amp;
    } else {
        v = (i == j) ? 1.f : 0.f;
    }
    g_K[(size_t)kap * NPn * NPn + (size_t)i * NPn + j] = v;
}

// ---------------- build K_nt ----------------
__global__ void build_knt_kernel(const float* __restrict__ theta0,
                                 const float* __restrict__ theta,
                                 const float* __restrict__ Lmb) {
    int kap = blockIdx.z;
    int o = blockIdx.y * 16 + threadIdx.y;
    int n = blockIdx.x * 16 + threadIdx.x;
    __shared__ float to_[16][Dn], tn_[16][Dn];
    __shared__ float s_ils[Dn];
    __shared__ float s_amp;
    int t = threadIdx.y * 16 + threadIdx.x;
    if (t < 16 * Dn) {
        int r = t / Dn, d = t % Dn;
        int go = blockIdx.y * 16 + r;
        to_[r][d] = (go < N0n) ? theta0[go * Dn + d] : 0.f;
        int gn = blockIdx.x * 16 + r;
        tn_[r][d] = (gn < Nn) ? theta[gn * Dn + d] : 0.f;
    }
    if (threadIdx.y == 15) {
        if (threadIdx.x < Dn) s_ils[threadIdx.x] = expf(-Lmb[kap * (Dn + 1) + threadIdx.x]);
        if (threadIdx.x == Dn) s_amp = expf(Lmb[kap * (Dn + 1) + Dn]);
    }
    __syncthreads();
    if (o >= N0n || n >= Nn) return;
    float prod = 1.f, ssum = 0.f;
#pragma unroll
    for (int d = 0; d < Dn; d++) {
        float S = fabsf(to_[threadIdx.y][d] - tn_[threadIdx.x][d]) * s_ils[d];
        prod *= (1.f + S);
        ssum += S;
    }
    g_Knt[(size_t)(kap * N0n + o) * Nn + n] = s_amp * prod * fast_expn(ssum);
}

// ---------------- rhs init ----------------
__global__ void init_rhs_kernel(const float* __restrict__ Mu) {
    int idx = blockIdx.x * blockDim.x + threadIdx.x;
    if (idx >= KAPn * NPn) return;
    int kap = idx / NPn, i = idx % NPn;
    g_rhs[idx] = (i < Nn) ? Mu[kap * Nn + i] : 0.f;
}

// ---------------- Cholesky: factor 128x128 diag block ------------------------
// Deferred scaling, ONE barrier per column: every thread redundantly computes
// the clamped rsqrt from a shared broadcast (no serial tid-0 phase).
__global__ void __launch_bounds__(512) potf2_kernel(const float* __restrict__ Lmb, int off) {
    extern __shared__ float sm[];
    float* sh = sm;                  // [128][129]
    float* sdi = sm + NBn * (NBn + 1);
    int kap = blockIdx.x;
    int tid = threadIdx.x;
    int t = tid & 127, q = tid >> 7;
    float* A = g_K + (size_t)kap * NPn * NPn + (size_t)off * NPn + off;
    for (int idx = tid; idx < NBn * NBn; idx += 512) {
        int r = idx >> 7, c = idx & 127;
        sh[r * (NBn + 1) + c] = A[r * NPn + c];
    }
    __shared__ float s_dmin;
    if (tid == 0) s_dmin = 1e-4f * expf(Lmb[kap * (Dn + 1) + Dn]);
    __syncthreads();
    float dmin = s_dmin;
    for (int j = 0; j < NBn; j++) {
        float d = sh[j * (NBn + 1) + j];        // broadcast read
        if (!(d > dmin)) d = dmin;              // clamp (also catches NaN)
        float rinv = rsqrtf(d);
        if (tid == 0) { sdi[j] = rinv; sh[j * (NBn + 1) + j] = d; }  // store clamped d
        if (t > j) {
            float ltj = sh[t * (NBn + 1) + j] * (rinv * rinv);
            int lo = q * 32; if (lo < j + 1) lo = j + 1;
            int hi = q * 32 + 31; if (hi > t) hi = t;
            for (int i = lo; i <= hi; i++)
                sh[t * (NBn + 1) + i] -= ltj * sh[i * (NBn + 1) + j];
        }
        __syncthreads();
    }
    // writeback with deferred scaling: lower *= sdi[col]; diag = d * rsqrt(d) = sqrt(d)
    for (int idx = tid; idx < NBn * NBn; idx += 512) {
        int r = idx >> 7, c = idx & 127;
        float v = sh[r * (NBn + 1) + c];
        if (r >= c) v *= sdi[c];
        else       v = sh[r * (NBn + 1) + c];   // upper junk, harmless
        if (r == c) v = sh[r * (NBn + 1) + c] * sdi[c];  // sqrt(d)
        A[r * NPn + c] = v;
    }
    if (tid < NBn) g_invd[kap * NPn + off + tid] = sdi[tid];
}

// ---------------- Cholesky panel trsm: L21 = A21 * L11^{-T} ----------------
// Warp processes 4 rows IN THE SAME substitution chain: 4 independent shfls per
// column, L-column LDS amortized across the 4 rows.
__global__ void __launch_bounds__(256) trsm_kernel(int off, int m) {
    extern __shared__ float sm[];
    float* Ls = sm;                  // [128][129]
    float* sinv = sm + NBn * (NBn + 1);
    int kap = blockIdx.y;
    int tid = threadIdx.x;
    float* G = g_K + (size_t)kap * NPn * NPn;
    const float* L11 = G + (size_t)off * NPn + off;
    for (int idx = tid; idx < NBn * NBn; idx += 256) {
        int r = idx >> 7, c = idx & 127;
        Ls[r * (NBn + 1) + c] = L11[r * NPn + c];
    }
    if (tid < NBn) sinv[tid] = g_invd[kap * NPn + off + tid];
    __syncthreads();
    int w = tid >> 5, lane = tid & 31;
    int row0 = off + NBn + blockIdx.x * 32 + w * 4;
    float x[4][4];                   // [row][quarter]
#pragma unroll
    for (int rr = 0; rr < 4; rr++) {
        const float* arow = G + (size_t)(row0 + rr) * NPn + off;
#pragma unroll
        for (int qq = 0; qq < 4; qq++) x[rr][qq] = arow[lane + 32 * qq];
    }
#pragma unroll
    for (int qj = 0; qj < 4; qj++) {
#pragma unroll
        for (int lj = 0; lj < 32; lj++) {
            int j = qj * 32 + lj;
            float sv = sinv[j];
            if (lane == lj) {
#pragma unroll
                for (int rr = 0; rr < 4; rr++) x[rr][qj] *= sv;
            }
            float xj[4];
#pragma unroll
            for (int rr = 0; rr < 4; rr++) xj[rr] = __shfl_sync(0xffffffffu, x[rr][qj], lj);
#pragma unroll
            for (int qq = qj; qq < 4; qq++) {
                float Lv = Ls[(lane + 32 * qq) * (NBn + 1) + j];
                bool act = (qq > qj) || (lane > lj);
                if (act) {
#pragma unroll
                    for (int rr = 0; rr < 4; rr++) x[rr][qq] -= xj[rr] * Lv;
                }
            }
        }
    }
#pragma unroll
    for (int rr = 0; rr < 4; rr++) {
        float* arow = G + (size_t)(row0 + rr) * NPn + off;
#pragma unroll
        for (int qq = 0; qq < 4; qq++) arow[lane + 32 * qq] = x[rr][qq];
    }
}

// ---------------- Cholesky: trailing SYRK update (lower-tri tiles only) ------
// 2 CTAs/SM forced; k-chunk 32 halves barrier count.
__global__ void __launch_bounds__(256, 2) syrk_kernel(int off, int nb) {
    int kap = blockIdx.y;
    int tt = blockIdx.x;
    int bi = 0, rem = tt;
    while (rem > bi) { rem -= (bi + 1); bi++; }
    int bj = rem;                     // bi >= bj
    int r0 = off + NBn;
    int R = r0 + bi * NBn, C = r0 + bj * NBn;
    float* G = g_K + (size_t)kap * NPn * NPn;

    __shared__ float As[KCH][NBn + 4];
    __shared__ float Bs[KCH][NBn + 4];
    float acc[8][8];
#pragma unroll
    for (int m = 0; m < 8; m++)
#pragma unroll
        for (int n = 0; n < 8; n++) acc[m][n] = 0.f;

    int tid = threadIdx.x;
    int tr = tid >> 4, tc = tid & 15;

    for (int kk = 0; kk < NBn; kk += KCH) {
#pragma unroll
        for (int s = 0; s < 4; s++) {
            int fi = tid + s * 256;       // float4 index in [0,1024)
            int row = fi >> 3;            // 8 float4 per 32-float row
            int kq = (fi & 7) * 4;
            float4 av = *(const float4*)(G + (size_t)(R + row) * NPn + off + kk + kq);
            As[kq + 0][row] = av.x; As[kq + 1][row] = av.y;
            As[kq + 2][row] = av.z; As[kq + 3][row] = av.w;
            float4 bv = *(const float4*)(G + (size_t)(C + row) * NPn + off + kk + kq);
            Bs[kq + 0][row] = bv.x; Bs[kq + 1][row] = bv.y;
            Bs[kq + 2][row] = bv.z; Bs[kq + 3][row] = bv.w;
        }
        __syncthreads();
#pragma unroll
        for (int k = 0; k < KCH; k++) {
            float ar[8], br[8];
#pragma unroll
            for (int m = 0; m < 8; m++) ar[m] = As[k][tr * 8 + m];
#pragma unroll
            for (int n = 0; n < 8; n++) br[n] = Bs[k][tc * 8 + n];
#pragma unroll
            for (int m = 0; m < 8; m++)
#pragma unroll
                for (int n = 0; n < 8; n++) acc[m][n] += ar[m] * br[n];
        }
        __syncthreads();
    }
#pragma unroll
    for (int m = 0; m < 8; m++) {
        float* crow = G + (size_t)(R + tr * 8 + m) * NPn + C + tc * 8;
#pragma unroll
        for (int n = 0; n < 8; n++) crow[n] -= acc[m][n];
    }
}

// ---------------- fused forward solve: L y = rhs (one CTA per kap) ----------
__global__ void __launch_bounds__(1024) fwd_solve_kernel() {
    extern __shared__ float sm[];
    float* Ls = sm;                               // [128][129]
    float* sinv = sm + NBn * (NBn + 1);           // [128]
    float* sr = sinv + NBn;                       // [2048]
    int kap = blockIdx.x;
    int tid = threadIdx.x;
    const float* G = g_K + (size_t)kap * NPn * NPn;
    float* r = g_rhs + kap * NPn;
    for (int i = tid; i < NPn; i += 1024) sr[i] = r[i];
    for (int k = 0; k < NSTEPS; k++) {
        int off = k * NBn;
        const float* L11 = G + (size_t)off * NPn + off;
        for (int idx = tid; idx < NBn * NBn; idx += 1024) {
            int rr = idx >> 7, c = idx & 127;
            Ls[rr * (NBn + 1) + c] = L11[rr * NPn + c];
        }
        if (tid < NBn) sinv[tid] = g_invd[kap * NPn + off + tid];
        __syncthreads();
        if (tid < 32) {                            // warp 0 does 128-substitution
            int lane = tid;
            float x[4];
#pragma unroll
            for (int qq = 0; qq < 4; qq++) x[qq] = sr[off + lane + 32 * qq];
#pragma unroll
            for (int qj = 0; qj < 4; qj++) {
#pragma unroll
                for (int lj = 0; lj < 32; lj++) {
                    int j = qj * 32 + lj;
                    if (lane == lj) x[qj] *= sinv[j];
                    float xj = __shfl_sync(0xffffffffu, x[qj], lj);
                    if (lane > lj) x[qj] -= xj * Ls[(lane + 32 * qj) * (NBn + 1) + j];
#pragma unroll
                    for (int qq = qj + 1; qq < 4; qq++)
                        x[qq] -= xj * Ls[(lane + 32 * qq) * (NBn + 1) + j];
                }
            }
#pragma unroll
            for (int qq = 0; qq < 4; qq++) sr[off + lane + 32 * qq] = x[qq];
        }
        __syncthreads();
        // update rows below: warp per row, one LDG.128 per lane per row
        int wid = tid >> 5, lane = tid & 31;
        const float4* srv = (const float4*)(sr + off);
        float4 b = srv[lane];
        for (int row = off + NBn + wid; row < NPn; row += 32) {
            const float4* Lr = (const float4*)(G + (size_t)row * NPn + off);
            float4 a = Lr[lane];
            float part = a.x * b.x + a.y * b.y + a.z * b.z + a.w * b.w;
            part = warp_reduce(part);
            if (lane == 0) sr[row] -= part;
        }
        __syncthreads();
    }
    for (int i = tid; i < NPn; i += 1024) r[i] = sr[i];
}

// ---------------- fused backward solve: L^T x = y (one CTA per kap) ---------
__global__ void __launch_bounds__(1024) bwd_solve_kernel() {
    extern __shared__ float sm[];
    float* Ls = sm;
    float* sinv = sm + NBn * (NBn + 1);
    float* sr = sinv + NBn;
    int kap = blockIdx.x;
    int tid = threadIdx.x;
    const float* G = g_K + (size_t)kap * NPn * NPn;
    float* r = g_rhs + kap * NPn;
    for (int i = tid; i < NPn; i += 1024) sr[i] = r[i];
    for (int k = NSTEPS - 1; k >= 0; k--) {
        int off = k * NBn;
        const float* L11 = G + (size_t)off * NPn + off;
        for (int idx = tid; idx < NBn * NBn; idx += 1024) {
            int rr = idx >> 7, c = idx & 127;
            Ls[rr * (NBn + 1) + c] = L11[rr * NPn + c];
        }
        if (tid < NBn) sinv[tid] = g_invd[kap * NPn + off + tid];
        __syncthreads();
        if (tid < 32) {                            // warp 0: solve L11^T x = r
            int lane = tid;
            float x[4];
#pragma unroll
            for (int qq = 0; qq < 4; qq++) x[qq] = sr[off + lane + 32 * qq];
#pragma unroll
            for (int qj = 3; qj >= 0; qj--) {
#pragma unroll
                for (int lj = 31; lj >= 0; lj--) {
                    int j = qj * 32 + lj;
                    if (lane == lj) x[qj] *= sinv[j];
                    float xj = __shfl_sync(0xffffffffu, x[qj], lj);
                    if (lane < lj) x[qj] -= xj * Ls[j * (NBn + 1) + lane + 32 * qj];
#pragma unroll
                    for (int qq = 0; qq < qj; qq++)
                        x[qq] -= xj * Ls[j * (NBn + 1) + lane + 32 * qq];
                }
            }
#pragma unroll
            for (int qq = 0; qq < 4; qq++) sr[off + lane + 32 * qq] = x[qq];
        }
        __syncthreads();
        // update sr[0..off): float4 per thread, coalesced row reads
        float4* srv = (float4*)sr;
        for (int c4 = tid; c4 < off / 4; c4 += 1024) {
            const float4* col = (const float4*)(G + (size_t)off * NPn) + c4;
            float4 s = make_float4(0.f, 0.f, 0.f, 0.f);
#pragma unroll 8
            for (int i = 0; i < NBn; i++) {
                float4 v = col[(size_t)i * (NPn / 4)];
                float xv = sr[off + i];
                s.x += v.x * xv; s.y += v.y * xv; s.z += v.z * xv; s.w += v.w * xv;
            }
            float4 cur = srv[c4];
            cur.x -= s.x; cur.y -= s.y; cur.z -= s.z; cur.w -= s.w;
            srv[c4] = cur;
        }
        __syncthreads();
    }
    for (int i = tid; i < NPn; i += 1024) r[i] = sr[i];
}

// ---------------- ghat = K_nt @ alpha (warp per output) ----------------
__global__ void ghat_kernel() {
    int gw = (blockIdx.x * blockDim.x + threadIdx.x) >> 5;
    int lane = threadIdx.x & 31;
    if (gw >= KAPn * N0n) return;
    int kap = gw / N0n, o = gw % N0n;
    const float* Kr = g_Knt + (size_t)(kap * N0n + o) * Nn;
    const float* a = g_rhs + kap * NPn;
    float s = 0.f;
    for (int i = lane * 4; i < Nn; i += 128) {
        float4 kv = *(const float4*)(Kr + i);
        float4 av = *(const float4*)(a + i);
        s += kv.x * av.x + kv.y * av.y + kv.z * av.z + kv.w * av.w;
    }
    s = warp_reduce(s);
    if (lane == 0) g_ghat[kap * N0n + o] = s;
}

// ---------------- fhat = psi + Phi @ ghat ----------------
__global__ void fhat_kernel(const float* __restrict__ psi,
                            const float* __restrict__ Phi,
                            float* __restrict__ out) {
    int idx = blockIdx.x * blockDim.x + threadIdx.x;
    if (idx >= Mn * N0n) return;
    int m = idx / N0n, o = idx % N0n;
    float s = psi[m];
#pragma unroll
    for (int k = 0; k < KAPn; k++) s += Phi[m * KAPn + k] * g_ghat[k * N0n + o];
    out[idx] = s;
}

// ---------------- host launch ----------------
extern "C" void kernel_launch(void* const* d_in, const int* in_sizes, int n_in,
                              void* d_out, int out_size) {
    const float* theta0 = (const float*)d_in[0];
    const float* Lmb    = (const float*)d_in[1];
    // d_in[2] = lsigma2 (unused by fhat)
    const float* Mu     = (const float*)d_in[3];
    const float* psi    = (const float*)d_in[4];
    const float* Phi    = (const float*)d_in[5];
    const float* theta  = (const float*)d_in[6];
    float* out = (float*)d_out;

    const int SMEM_FACT  = (NBn * (NBn + 1) + NBn) * (int)sizeof(float);          // 66560
    const int SMEM_SOLVE = (NBn * (NBn + 1) + NBn + NPn) * (int)sizeof(float);    // 74752
    cudaFuncSetAttribute(potf2_kernel,     cudaFuncAttributeMaxDynamicSharedMemorySize, SMEM_FACT);
    cudaFuncSetAttribute(trsm_kernel,      cudaFuncAttributeMaxDynamicSharedMemorySize, SMEM_FACT);
    cudaFuncSetAttribute(fwd_solve_kernel, cudaFuncAttributeMaxDynamicSharedMemorySize, SMEM_SOLVE);
    cudaFuncSetAttribute(bwd_solve_kernel, cudaFuncAttributeMaxDynamicSharedMemorySize, SMEM_SOLVE);

    // Launch order chosen so the profiled launch (#3) is syrk step 0.
    build_ktt_kernel<<<dim3(NPn / 16, NPn / 16, KAPn), dim3(16, 16)>>>(theta, Lmb);

    // step 0 of blocked Cholesky
    potf2_kernel<<<KAPn, 512, SMEM_FACT>>>(Lmb, 0);
    {
        int m = NPn - NBn;
        trsm_kernel<<<dim3(m / 32, KAPn), 256, SMEM_FACT>>>(0, m);
        int nb = m / NBn;
        syrk_kernel<<<dim3(nb * (nb + 1) / 2, KAPn), 256>>>(0, nb);   // launch #3
    }

    build_knt_kernel<<<dim3((Nn + 15) / 16, (N0n + 15) / 16, KAPn), dim3(16, 16)>>>(theta0, theta, Lmb);
    init_rhs_kernel<<<(KAPn * NPn + 255) / 256, 256>>>(Mu);

    // remaining Cholesky steps
    for (int k = 1; k < NSTEPS; k++) {
        int off = k * NBn;
        potf2_kernel<<<KAPn, 512, SMEM_FACT>>>(Lmb, off);
        int m = NPn - off - NBn;
        if (m > 0) {
            trsm_kernel<<<dim3(m / 32, KAPn), 256, SMEM_FACT>>>(off, m);
            int nb = m / NBn;
            syrk_kernel<<<dim3(nb * (nb + 1) / 2, KAPn), 256>>>(off, nb);
        }
    }

    fwd_solve_kernel<<<KAPn, 1024, SMEM_SOLVE>>>();
    bwd_solve_kernel<<<KAPn, 1024, SMEM_SOLVE>>>();

    ghat_kernel<<<(KAPn * N0n * 32 + 255) / 256, 256>>>();
    fhat_kernel<<<(Mn * N0n + 255) / 256, 256>>>(psi, Phi, out);
}